// round 2
// baseline (speedup 1.0000x reference)
#include <cuda_runtime.h>
#include <cuda_fp16.h>
#include <stdint.h>

// ---------------- problem constants ----------------
constexpr int kE   = 8;
constexpr int kH   = 1024;
constexpr int kF   = 4096;
constexpr int kDL  = 256;
constexpr int kTPE = 1024;
constexpr int kTok = kE * kTPE;   // 8192

// ---------------- tiling ----------------
constexpr int BM = 128, BN = 128, BK = 64;
constexpr int LDSA  = BK + 8;     // 72 halves per A-tile row (padded, conflict-free ldmatrix)
constexpr int LDSB  = BK + 8;     // 72 halves per B-tile row (NT gemms, [n][k])
constexpr int LDSB3 = BN + 8;     // 136 halves per B-tile row (gemm3, [k][n])

constexpr int STG12 = BM * LDSA + BN * LDSB;   // halves per pipeline stage (gemm12)
constexpr int STG3  = BM * LDSA + BK * LDSB3;  // halves per pipeline stage (gemm3)
constexpr int SMEM12 = 2 * STG12 * 2;          // bytes (2 stages)
constexpr int SMEM3  = 2 * STG3  * 2;

// ---------------- fp16 scratch (device globals: no allocation allowed) ----------------
__device__ __half g_xh [(size_t)kTok * kH];        // 16 MB
__device__ __half g_ah [(size_t)kTok * kDL];       //  4 MB
__device__ __half g_wup[(size_t)kE * kF * kDL];    // 16 MB
__device__ __half g_v1 [(size_t)kE * kF * kH];     // 64 MB
__device__ __half g_w2 [(size_t)kE * kF * kH];     // 64 MB
__device__ __half g_hh [(size_t)kTok * kF];        // 64 MB  (silu(x1)*x2)

// ---------------- PTX helpers ----------------
__device__ __forceinline__ uint32_t smem_u32(const void* p) {
    uint32_t r;
    asm volatile("{ .reg .u64 t; cvta.to.shared.u64 t, %1; cvt.u32.u64 %0, t; }"
                 : "=r"(r) : "l"(p));
    return r;
}
__device__ __forceinline__ void cp16(uint32_t dst, const void* src) {
    asm volatile("cp.async.cg.shared.global [%0], [%1], 16;" :: "r"(dst), "l"(src));
}
__device__ __forceinline__ void cp_commit() { asm volatile("cp.async.commit_group;"); }
template <int N> __device__ __forceinline__ void cp_wait() {
    asm volatile("cp.async.wait_group %0;" :: "n"(N));
}
__device__ __forceinline__ void ldsm4(uint32_t* r, uint32_t a) {
    asm volatile("ldmatrix.sync.aligned.m8n8.x4.shared.b16 {%0,%1,%2,%3},[%4];"
                 : "=r"(r[0]), "=r"(r[1]), "=r"(r[2]), "=r"(r[3]) : "r"(a));
}
__device__ __forceinline__ void ldsm4t(uint32_t* r, uint32_t a) {
    asm volatile("ldmatrix.sync.aligned.m8n8.x4.trans.shared.b16 {%0,%1,%2,%3},[%4];"
                 : "=r"(r[0]), "=r"(r[1]), "=r"(r[2]), "=r"(r[3]) : "r"(a));
}
__device__ __forceinline__ void mma16816(float* c, const uint32_t* a, uint32_t b0, uint32_t b1) {
    asm volatile(
        "mma.sync.aligned.m16n8k16.row.col.f32.f16.f16.f32 "
        "{%0,%1,%2,%3},{%4,%5,%6,%7},{%8,%9},{%0,%1,%2,%3};"
        : "+f"(c[0]), "+f"(c[1]), "+f"(c[2]), "+f"(c[3])
        : "r"(a[0]), "r"(a[1]), "r"(a[2]), "r"(a[3]), "r"(b0), "r"(b1));
}

// ---------------- fp32 -> fp16 conversion ----------------
__global__ void k_cvt(const float* __restrict__ s, __half* __restrict__ d, int n4) {
    for (int i = blockIdx.x * blockDim.x + threadIdx.x; i < n4; i += gridDim.x * blockDim.x) {
        float4 v = reinterpret_cast<const float4*>(s)[i];
        reinterpret_cast<__half2*>(d)[2 * i]     = __floats2half2_rn(v.x, v.y);
        reinterpret_cast<__half2*>(d)[2 * i + 1] = __floats2half2_rn(v.z, v.w);
    }
}

// ---------------- tile loaders (cp.async, 16B vectors) ----------------
__device__ __forceinline__ void load_nt(const __half* gA, int ldA, const __half* gB, int ldB,
                                        int kBase, __half* sA, __half* sB, int tid) {
    // A: 128 rows x 64 halves; B: 128 rows x 64 halves   (both K-major)
#pragma unroll
    for (int i = 0; i < 4; i++) {
        int v = tid + i * 256;
        int row = v >> 3, c = (v & 7) * 8;
        cp16(smem_u32(sA + row * LDSA + c), gA + (size_t)row * ldA + kBase + c);
    }
#pragma unroll
    for (int i = 0; i < 4; i++) {
        int v = tid + i * 256;
        int row = v >> 3, c = (v & 7) * 8;
        cp16(smem_u32(sB + row * LDSB + c), gB + (size_t)row * ldB + kBase + c);
    }
}

__device__ __forceinline__ void load_nn(const __half* gA, int ldA, const __half* gB, int ldB,
                                        int kBase, __half* sA, __half* sB, int tid) {
    // A: 128 rows x 64 halves (K-major). B: 64 k-rows x 128 n-halves.
#pragma unroll
    for (int i = 0; i < 4; i++) {
        int v = tid + i * 256;
        int row = v >> 3, c = (v & 7) * 8;
        cp16(smem_u32(sA + row * LDSA + c), gA + (size_t)row * ldA + kBase + c);
    }
#pragma unroll
    for (int i = 0; i < 4; i++) {
        int v = tid + i * 256;
        int row = v >> 4, c = (v & 15) * 8;
        cp16(smem_u32(sB + row * LDSB3 + c), gB + (size_t)(kBase + row) * ldB + c);
    }
}

// ---------------- per-chunk MMA (warp tile 32x64: 2 m-tiles x 8 n-tiles) ----------------
__device__ __forceinline__ void mma_nt(const __half* sA, const __half* sB,
                                       float (&acc)[2][8][4], int wm, int wn, int lane) {
#pragma unroll
    for (int kk = 0; kk < BK; kk += 16) {
        uint32_t a[2][4];
#pragma unroll
        for (int im = 0; im < 2; im++) {
            const __half* p = sA + (wm * 32 + im * 16 + (lane & 15)) * LDSA + kk + (lane >> 4) * 8;
            ldsm4(a[im], smem_u32(p));
        }
#pragma unroll
        for (int j = 0; j < 4; j++) {
            const __half* p = sB + (wn * 64 + j * 16 + (lane & 7) + ((lane >> 4) << 3)) * LDSB
                               + kk + ((lane >> 3) & 1) * 8;
            uint32_t b[4];
            ldsm4(b, smem_u32(p));
#pragma unroll
            for (int im = 0; im < 2; im++) {
                mma16816(acc[im][2 * j],     a[im], b[0], b[1]);
                mma16816(acc[im][2 * j + 1], a[im], b[2], b[3]);
            }
        }
    }
}

__device__ __forceinline__ void mma_nn(const __half* sA, const __half* sB,
                                       float (&acc)[2][8][4], int wm, int wn, int lane) {
#pragma unroll
    for (int kk = 0; kk < BK; kk += 16) {
        uint32_t a[2][4];
#pragma unroll
        for (int im = 0; im < 2; im++) {
            const __half* p = sA + (wm * 32 + im * 16 + (lane & 15)) * LDSA + kk + (lane >> 4) * 8;
            ldsm4(a[im], smem_u32(p));
        }
#pragma unroll
        for (int j = 0; j < 4; j++) {
            const __half* p = sB + (kk + (lane & 7) + ((lane >> 3) & 1) * 8) * LDSB3
                               + wn * 64 + j * 16 + (lane >> 4) * 8;
            uint32_t b[4];
            ldsm4t(b, smem_u32(p));
#pragma unroll
            for (int im = 0; im < 2; im++) {
                mma16816(acc[im][2 * j],     a[im], b[0], b[1]);
                mma16816(acc[im][2 * j + 1], a[im], b[2], b[3]);
            }
        }
    }
}

// ---------------- double-buffered K pipelines ----------------
__device__ __forceinline__ void pipe_nt(const __half* gA, int ldA, const __half* gB, int ldB,
                                        int nCh, __half* smem, float (&acc)[2][8][4],
                                        int tid, int wm, int wn, int lane) {
    __half* sA0 = smem;          __half* sB0 = smem + BM * LDSA;
    __half* sA1 = smem + STG12;  __half* sB1 = sA1 + BM * LDSA;
    load_nt(gA, ldA, gB, ldB, 0, sA0, sB0, tid);
    cp_commit();
    for (int kc = 0; kc < nCh; kc++) {
        __half* cA = (kc & 1) ? sA1 : sA0;
        __half* cB = (kc & 1) ? sB1 : sB0;
        if (kc + 1 < nCh) {
            __half* nA = (kc & 1) ? sA0 : sA1;
            __half* nB = (kc & 1) ? sB0 : sB1;
            load_nt(gA, ldA, gB, ldB, (kc + 1) * BK, nA, nB, tid);
            cp_commit();
            cp_wait<1>();
        } else {
            cp_wait<0>();
        }
        __syncthreads();
        mma_nt(cA, cB, acc, wm, wn, lane);
        __syncthreads();
    }
}

__device__ __forceinline__ void pipe_nn(const __half* gA, int ldA, const __half* gB, int ldB,
                                        int nCh, __half* smem, float (&acc)[2][8][4],
                                        int tid, int wm, int wn, int lane) {
    __half* sA0 = smem;         __half* sB0 = smem + BM * LDSA;
    __half* sA1 = smem + STG3;  __half* sB1 = sA1 + BM * LDSA;
    load_nn(gA, ldA, gB, ldB, 0, sA0, sB0, tid);
    cp_commit();
    for (int kc = 0; kc < nCh; kc++) {
        __half* cA = (kc & 1) ? sA1 : sA0;
        __half* cB = (kc & 1) ? sB1 : sB0;
        if (kc + 1 < nCh) {
            __half* nA = (kc & 1) ? sA0 : sA1;
            __half* nB = (kc & 1) ? sB0 : sB1;
            load_nn(gA, ldA, gB, ldB, (kc + 1) * BK, nA, nB, tid);
            cp_commit();
            cp_wait<1>();
        } else {
            cp_wait<0>();
        }
        __syncthreads();
        mma_nn(cA, cB, acc, wm, wn, lane);
        __syncthreads();
    }
}

// ---------------- kernel 1: x1 = acts@wup^T, x2 = x@v1^T, h = silu(x1)*x2 ----------------
__global__ void __launch_bounds__(256, 1) k_gemm12() {
    extern __shared__ __half smem[];
    const int tid = threadIdx.x, lane = tid & 31, warp = tid >> 5;
    const int wm = warp & 3, wn = warp >> 2;
    const int e = blockIdx.z, mt = blockIdx.y, nt = blockIdx.x;

    const __half* A1 = g_ah  + (size_t)(e * kTPE + mt * BM) * kDL;
    const __half* B1 = g_wup + ((size_t)e * kF + nt * BN) * kDL;
    const __half* A2 = g_xh  + (size_t)(e * kTPE + mt * BM) * kH;
    const __half* B2 = g_v1  + ((size_t)e * kF + nt * BN) * kH;

    float acc[2][8][4];
#pragma unroll
    for (int i = 0; i < 2; i++)
#pragma unroll
        for (int j = 0; j < 8; j++)
#pragma unroll
            for (int r = 0; r < 4; r++) acc[i][j][r] = 0.f;

    // GEMM1: K = DL = 256
    pipe_nt(A1, kDL, B1, kDL, kDL / BK, smem, acc, tid, wm, wn, lane);

    // silu(x1), keep as packed fp16 (32 regs), then reuse acc for GEMM2
    __half2 sf[2][8][2];
#pragma unroll
    for (int i = 0; i < 2; i++)
#pragma unroll
        for (int j = 0; j < 8; j++) {
#pragma unroll
            for (int p = 0; p < 2; p++) {
                float x0 = acc[i][j][2 * p], x1 = acc[i][j][2 * p + 1];
                float s0 = x0 / (1.f + __expf(-x0));
                float s1 = x1 / (1.f + __expf(-x1));
                sf[i][j][p] = __floats2half2_rn(s0, s1);
            }
            acc[i][j][0] = acc[i][j][1] = acc[i][j][2] = acc[i][j][3] = 0.f;
        }

    // GEMM2: K = H = 1024
    pipe_nt(A2, kH, B2, kH, kH / BK, smem, acc, tid, wm, wn, lane);

    // epilogue: h = silu(x1) * x2  -> fp16 scratch
    const int rBase = e * kTPE + mt * BM + wm * 32 + (lane >> 2);
    const int cBase = nt * BN + wn * 64 + (lane & 3) * 2;
#pragma unroll
    for (int i = 0; i < 2; i++)
#pragma unroll
        for (int j = 0; j < 8; j++) {
            int r = rBase + i * 16;
            int c = cBase + j * 8;
            float2 s0 = __half22float2(sf[i][j][0]);
            float2 s1 = __half22float2(sf[i][j][1]);
            __half2 h0 = __floats2half2_rn(s0.x * acc[i][j][0], s0.y * acc[i][j][1]);
            __half2 h1 = __floats2half2_rn(s1.x * acc[i][j][2], s1.y * acc[i][j][3]);
            *reinterpret_cast<__half2*>(&g_hh[(size_t)r * kF + c])       = h0;
            *reinterpret_cast<__half2*>(&g_hh[(size_t)(r + 8) * kF + c]) = h1;
        }
}

// ---------------- kernel 2: out = h @ w2 ----------------
__global__ void __launch_bounds__(256, 1) k_gemm3(float* __restrict__ out) {
    extern __shared__ __half smem[];
    const int tid = threadIdx.x, lane = tid & 31, warp = tid >> 5;
    const int wm = warp & 3, wn = warp >> 2;
    const int e = blockIdx.z, mt = blockIdx.y, nt = blockIdx.x;

    const __half* A = g_hh + (size_t)(e * kTPE + mt * BM) * kF;
    const __half* B = g_w2 + (size_t)e * kF * kH + nt * BN;

    float acc[2][8][4];
#pragma unroll
    for (int i = 0; i < 2; i++)
#pragma unroll
        for (int j = 0; j < 8; j++)
#pragma unroll
            for (int r = 0; r < 4; r++) acc[i][j][r] = 0.f;

    pipe_nn(A, kF, B, kH, kF / BK, smem, acc, tid, wm, wn, lane);

    const int rBase = e * kTPE + mt * BM + wm * 32 + (lane >> 2);
    const int cBase = nt * BN + wn * 64 + (lane & 3) * 2;
#pragma unroll
    for (int i = 0; i < 2; i++)
#pragma unroll
        for (int j = 0; j < 8; j++) {
            int r = rBase + i * 16;
            int c = cBase + j * 8;
            float2 v0 = make_float2(acc[i][j][0], acc[i][j][1]);
            float2 v1 = make_float2(acc[i][j][2], acc[i][j][3]);
            *reinterpret_cast<float2*>(&out[(size_t)r * kH + c])       = v0;
            *reinterpret_cast<float2*>(&out[(size_t)(r + 8) * kH + c]) = v1;
        }
}

// ---------------- launch ----------------
extern "C" void kernel_launch(void* const* d_in, const int* in_sizes, int n_in,
                              void* d_out, int out_size) {
    const float* x    = (const float*)d_in[0];
    const float* acts = (const float*)d_in[1];
    const float* wup  = (const float*)d_in[2];
    const float* v1   = (const float*)d_in[3];
    const float* w2   = (const float*)d_in[4];
    float* out = (float*)d_out;

    void *pxh, *pah, *pwup, *pv1, *pw2;
    cudaGetSymbolAddress(&pxh,  g_xh);
    cudaGetSymbolAddress(&pah,  g_ah);
    cudaGetSymbolAddress(&pwup, g_wup);
    cudaGetSymbolAddress(&pv1,  g_v1);
    cudaGetSymbolAddress(&pw2,  g_w2);

    cudaFuncSetAttribute(k_gemm12, cudaFuncAttributeMaxDynamicSharedMemorySize, SMEM12);
    cudaFuncSetAttribute(k_gemm3,  cudaFuncAttributeMaxDynamicSharedMemorySize, SMEM3);

    const int thr = 256, blk = 1184;  // 148 SMs * 8
    k_cvt<<<blk, thr>>>(x,    (__half*)pxh,  kTok * kH / 4);
    k_cvt<<<blk, thr>>>(acts, (__half*)pah,  kTok * kDL / 4);
    k_cvt<<<blk, thr>>>(wup,  (__half*)pwup, kE * kF * kDL / 4);
    k_cvt<<<blk, thr>>>(v1,   (__half*)pv1,  kE * kF * kH / 4);
    k_cvt<<<blk, thr>>>(w2,   (__half*)pw2,  kE * kF * kH / 4);

    dim3 g12(kF / BN, kTPE / BM, kE);   // f fastest -> expert weights stay L2-resident
    k_gemm12<<<g12, 256, SMEM12>>>();

    dim3 g3(kH / BN, kTPE / BM, kE);
    k_gemm3<<<g3, 256, SMEM3>>>(out);
}

// round 4
// speedup vs baseline: 1.1980x; 1.1980x over previous
#include <cuda_runtime.h>
#include <cuda_fp16.h>
#include <stdint.h>

// ---------------- problem constants ----------------
constexpr int kE   = 8;
constexpr int kH   = 1024;
constexpr int kF   = 4096;
constexpr int kDL  = 256;
constexpr int kTPE = 1024;
constexpr int kTok = kE * kTPE;   // 8192

// ---------------- tiling ----------------
constexpr int BM = 128, BN = 256, BK = 64;
constexpr int THREADS = 512;      // 16 warps: 4 (M) x 4 (N), warp tile 32x64
constexpr int STAGES = 3;

constexpr int LDSA  = BK + 8;     // 72 halves per A row
constexpr int LDSB  = BK + 8;     // 72 halves per B row (NT: [n][k])
constexpr int LDSB3 = BN + 8;     // 264 halves per B row (NN: [k][n])

constexpr int STG12 = BM * LDSA + BN * LDSB;   // halves per stage (gemm12)
constexpr int STG3  = BM * LDSA + BK * LDSB3;  // halves per stage (gemm3)
constexpr int SMEM12 = STAGES * STG12 * 2;     // 165888 B
constexpr int SMEM3  = STAGES * STG3  * 2;     // 156672 B

// ---------------- fp16 scratch (device globals: no allocation allowed) ----------------
__device__ __half g_xh [(size_t)kTok * kH];        // 16 MB
__device__ __half g_ah [(size_t)kTok * kDL];       //  4 MB
__device__ __half g_wup[(size_t)kE * kF * kDL];    // 16 MB
__device__ __half g_v1 [(size_t)kE * kF * kH];     // 64 MB
__device__ __half g_w2 [(size_t)kE * kF * kH];     // 64 MB
__device__ __half g_hh [(size_t)kTok * kF];        // 64 MB  (silu(x1)*x2)

// ---------------- PTX helpers ----------------
__device__ __forceinline__ uint32_t smem_u32(const void* p) {
    uint32_t r;
    asm volatile("{ .reg .u64 t; cvta.to.shared.u64 t, %1; cvt.u32.u64 %0, t; }"
                 : "=r"(r) : "l"(p));
    return r;
}
__device__ __forceinline__ void cp16(uint32_t dst, const void* src) {
    asm volatile("cp.async.cg.shared.global [%0], [%1], 16;" :: "r"(dst), "l"(src));
}
__device__ __forceinline__ void cp_commit() { asm volatile("cp.async.commit_group;"); }
template <int N> __device__ __forceinline__ void cp_wait() {
    asm volatile("cp.async.wait_group %0;" :: "n"(N));
}
__device__ __forceinline__ void ldsm4(uint32_t* r, uint32_t a) {
    asm volatile("ldmatrix.sync.aligned.m8n8.x4.shared.b16 {%0,%1,%2,%3},[%4];"
                 : "=r"(r[0]), "=r"(r[1]), "=r"(r[2]), "=r"(r[3]) : "r"(a));
}
__device__ __forceinline__ void ldsm4t(uint32_t* r, uint32_t a) {
    asm volatile("ldmatrix.sync.aligned.m8n8.x4.trans.shared.b16 {%0,%1,%2,%3},[%4];"
                 : "=r"(r[0]), "=r"(r[1]), "=r"(r[2]), "=r"(r[3]) : "r"(a));
}
__device__ __forceinline__ void mma16816(float* c, const uint32_t* a, uint32_t b0, uint32_t b1) {
    asm volatile(
        "mma.sync.aligned.m16n8k16.row.col.f32.f16.f16.f32 "
        "{%0,%1,%2,%3},{%4,%5,%6,%7},{%8,%9},{%0,%1,%2,%3};"
        : "+f"(c[0]), "+f"(c[1]), "+f"(c[2]), "+f"(c[3])
        : "r"(a[0]), "r"(a[1]), "r"(a[2]), "r"(a[3]), "r"(b0), "r"(b1));
}

// ---------------- fp32 -> fp16 conversion ----------------
__global__ void k_cvt(const float* __restrict__ s, __half* __restrict__ d, int n4) {
    for (int i = blockIdx.x * blockDim.x + threadIdx.x; i < n4; i += gridDim.x * blockDim.x) {
        float4 v = reinterpret_cast<const float4*>(s)[i];
        reinterpret_cast<__half2*>(d)[2 * i]     = __floats2half2_rn(v.x, v.y);
        reinterpret_cast<__half2*>(d)[2 * i + 1] = __floats2half2_rn(v.z, v.w);
    }
}

// ---------------- tile loaders (cp.async, 16B vectors, 512 threads) ----------------
__device__ __forceinline__ void load_nt(const __half* gA, int ldA, const __half* gB, int ldB,
                                        int kBase, __half* sA, __half* sB, int tid) {
    // A: 128 rows x 64 halves (1024 vec16); B: 256 rows x 64 halves (2048 vec16)
#pragma unroll
    for (int i = 0; i < 2; i++) {
        int v = tid + i * THREADS;
        int row = v >> 3, c = (v & 7) * 8;
        cp16(smem_u32(sA + row * LDSA + c), gA + (size_t)row * ldA + kBase + c);
    }
#pragma unroll
    for (int i = 0; i < 4; i++) {
        int v = tid + i * THREADS;
        int row = v >> 3, c = (v & 7) * 8;
        cp16(smem_u32(sB + row * LDSB + c), gB + (size_t)row * ldB + kBase + c);
    }
}

__device__ __forceinline__ void load_nn(const __half* gA, int ldA, const __half* gB, int ldB,
                                        int kBase, __half* sA, __half* sB, int tid) {
    // A: 128 rows x 64 halves. B: 64 k-rows x 256 n-halves (2048 vec16).
#pragma unroll
    for (int i = 0; i < 2; i++) {
        int v = tid + i * THREADS;
        int row = v >> 3, c = (v & 7) * 8;
        cp16(smem_u32(sA + row * LDSA + c), gA + (size_t)row * ldA + kBase + c);
    }
#pragma unroll
    for (int i = 0; i < 4; i++) {
        int v = tid + i * THREADS;
        int row = v >> 5, c = (v & 31) * 8;
        cp16(smem_u32(sB + row * LDSB3 + c), gB + (size_t)(kBase + row) * ldB + c);
    }
}

// ---------------- per-chunk MMA (warp tile 32x64: 2 m-tiles x 8 n-tiles) ----------------
__device__ __forceinline__ void mma_nt(const __half* sA, const __half* sB,
                                       float (&acc)[2][8][4], int wm, int wn, int lane) {
#pragma unroll
    for (int kk = 0; kk < BK; kk += 16) {
        uint32_t a[2][4];
#pragma unroll
        for (int im = 0; im < 2; im++) {
            const __half* p = sA + (wm * 32 + im * 16 + (lane & 15)) * LDSA + kk + (lane >> 4) * 8;
            ldsm4(a[im], smem_u32(p));
        }
#pragma unroll
        for (int j = 0; j < 4; j++) {
            const __half* p = sB + (wn * 64 + j * 16 + (lane & 7) + ((lane >> 4) << 3)) * LDSB
                               + kk + ((lane >> 3) & 1) * 8;
            uint32_t b[4];
            ldsm4(b, smem_u32(p));
#pragma unroll
            for (int im = 0; im < 2; im++) {
                mma16816(acc[im][2 * j],     a[im], b[0], b[1]);
                mma16816(acc[im][2 * j + 1], a[im], b[2], b[3]);
            }
        }
    }
}

__device__ __forceinline__ void mma_nn(const __half* sA, const __half* sB,
                                       float (&acc)[2][8][4], int wm, int wn, int lane) {
#pragma unroll
    for (int kk = 0; kk < BK; kk += 16) {
        uint32_t a[2][4];
#pragma unroll
        for (int im = 0; im < 2; im++) {
            const __half* p = sA + (wm * 32 + im * 16 + (lane & 15)) * LDSA + kk + (lane >> 4) * 8;
            ldsm4(a[im], smem_u32(p));
        }
#pragma unroll
        for (int j = 0; j < 4; j++) {
            const __half* p = sB + (kk + (lane & 7) + ((lane >> 3) & 1) * 8) * LDSB3
                               + wn * 64 + j * 16 + (lane >> 4) * 8;
            uint32_t b[4];
            ldsm4t(b, smem_u32(p));
#pragma unroll
            for (int im = 0; im < 2; im++) {
                mma16816(acc[im][2 * j],     a[im], b[0], b[1]);
                mma16816(acc[im][2 * j + 1], a[im], b[2], b[3]);
            }
        }
    }
}

// ==================== kernel 1: x1=acts@wup^T, x2=x@v1^T, h=silu(x1)*x2 ===========
__global__ void __launch_bounds__(THREADS, 1) k_gemm12() {
    extern __shared__ __half smem[];
    const int tid = threadIdx.x, lane = tid & 31, warp = tid >> 5;
    const int wm = warp & 3, wn = warp >> 2;
    const int nt = blockIdx.x, mt = blockIdx.y, e = blockIdx.z;

    const __half* A1 = g_ah  + (size_t)(e * kTPE + mt * BM) * kDL;
    const __half* B1 = g_wup + ((size_t)e * kF + nt * BN) * kDL;
    const __half* A2 = g_xh  + (size_t)(e * kTPE + mt * BM) * kH;
    const __half* B2 = g_v1  + ((size_t)e * kF + nt * BN) * kH;

    constexpr int NCH1 = kDL / BK;          // 4
    constexpr int NCH  = NCH1 + kH / BK;    // 20

    auto srcOf = [&](int c, const __half*& A, const __half*& B, int& la, int& lb, int& ko) {
        if (c < NCH1) { A = A1; B = B1; la = kDL; lb = kDL; ko = c * BK; }
        else          { A = A2; B = B2; la = kH;  lb = kH;  ko = (c - NCH1) * BK; }
    };

    float acc[2][8][4];
#pragma unroll
    for (int i = 0; i < 2; i++)
#pragma unroll
        for (int j = 0; j < 8; j++)
#pragma unroll
            for (int r = 0; r < 4; r++) acc[i][j][r] = 0.f;
    __half2 sf[2][8][2];

    // prologue: stages 0..STAGES-2
#pragma unroll
    for (int c = 0; c < STAGES - 1; c++) {
        const __half *A, *B; int la, lb, ko;
        srcOf(c, A, B, la, lb, ko);
        __half* sb = smem + c * STG12;
        load_nt(A, la, B, lb, ko, sb, sb + BM * LDSA, tid);
        cp_commit();
    }

    for (int kc = 0; kc < NCH; kc++) {
        cp_wait<STAGES - 2>();
        __syncthreads();
        const int pf = kc + STAGES - 1;
        if (pf < NCH) {
            const __half *A, *B; int la, lb, ko;
            srcOf(pf, A, B, la, lb, ko);
            __half* sb = smem + (pf % STAGES) * STG12;
            load_nt(A, la, B, lb, ko, sb, sb + BM * LDSA, tid);
        }
        cp_commit();

        if (kc == NCH1) {
            // acc holds x1 (gemm1 complete). silu -> fp16 regs, reset acc for gemm2.
#pragma unroll
            for (int i = 0; i < 2; i++)
#pragma unroll
                for (int j = 0; j < 8; j++) {
#pragma unroll
                    for (int p = 0; p < 2; p++) {
                        float x0 = acc[i][j][2 * p], x1 = acc[i][j][2 * p + 1];
                        sf[i][j][p] = __floats2half2_rn(x0 / (1.f + __expf(-x0)),
                                                        x1 / (1.f + __expf(-x1)));
                    }
                    acc[i][j][0] = acc[i][j][1] = acc[i][j][2] = acc[i][j][3] = 0.f;
                }
        }

        __half* cs = smem + (kc % STAGES) * STG12;
        mma_nt(cs, cs + BM * LDSA, acc, wm, wn, lane);
    }

    // epilogue: h = silu(x1) * x2 -> fp16 scratch
    const int rBase = e * kTPE + mt * BM + wm * 32 + (lane >> 2);
    const int cBase = nt * BN + wn * 64 + (lane & 3) * 2;
#pragma unroll
    for (int i = 0; i < 2; i++)
#pragma unroll
        for (int j = 0; j < 8; j++) {
            int r = rBase + i * 16;
            int c = cBase + j * 8;
            float2 s0 = __half22float2(sf[i][j][0]);
            float2 s1 = __half22float2(sf[i][j][1]);
            __half2 h0 = __floats2half2_rn(s0.x * acc[i][j][0], s0.y * acc[i][j][1]);
            __half2 h1 = __floats2half2_rn(s1.x * acc[i][j][2], s1.y * acc[i][j][3]);
            *reinterpret_cast<__half2*>(&g_hh[(size_t)r * kF + c])       = h0;
            *reinterpret_cast<__half2*>(&g_hh[(size_t)(r + 8) * kF + c]) = h1;
        }
}

// ==================== kernel 2: out = h @ w2 (NN) ====================
__global__ void __launch_bounds__(THREADS, 1) k_gemm3(float* __restrict__ out) {
    extern __shared__ __half smem[];
    const int tid = threadIdx.x, lane = tid & 31, warp = tid >> 5;
    const int wm = warp & 3, wn = warp >> 2;
    const int nt = blockIdx.x, mt = blockIdx.y, e = blockIdx.z;

    const __half* A = g_hh + (size_t)(e * kTPE + mt * BM) * kF;
    const __half* B = g_w2 + (size_t)e * kF * kH + nt * BN;
    constexpr int NCH = kF / BK;   // 64

    float acc[2][8][4];
#pragma unroll
    for (int i = 0; i < 2; i++)
#pragma unroll
        for (int j = 0; j < 8; j++)
#pragma unroll
            for (int r = 0; r < 4; r++) acc[i][j][r] = 0.f;

#pragma unroll
    for (int c = 0; c < STAGES - 1; c++) {
        __half* sb = smem + c * STG3;
        load_nn(A, kF, B, kH, c * BK, sb, sb + BM * LDSA, tid);
        cp_commit();
    }

    for (int kc = 0; kc < NCH; kc++) {
        cp_wait<STAGES - 2>();
        __syncthreads();
        const int pf = kc + STAGES - 1;
        if (pf < NCH) {
            __half* sb = smem + (pf % STAGES) * STG3;
            load_nn(A, kF, B, kH, pf * BK, sb, sb + BM * LDSA, tid);
        }
        cp_commit();
        __half* cs = smem + (kc % STAGES) * STG3;
        mma_nn(cs, cs + BM * LDSA, acc, wm, wn, lane);
    }

    const int rBase = e * kTPE + mt * BM + wm * 32 + (lane >> 2);
    const int cBase = nt * BN + wn * 64 + (lane & 3) * 2;
#pragma unroll
    for (int i = 0; i < 2; i++)
#pragma unroll
        for (int j = 0; j < 8; j++) {
            int r = rBase + i * 16;
            int c = cBase + j * 8;
            *reinterpret_cast<float2*>(&out[(size_t)r * kH + c]) =
                make_float2(acc[i][j][0], acc[i][j][1]);
            *reinterpret_cast<float2*>(&out[(size_t)(r + 8) * kH + c]) =
                make_float2(acc[i][j][2], acc[i][j][3]);
        }
}

// ---------------- launch ----------------
extern "C" void kernel_launch(void* const* d_in, const int* in_sizes, int n_in,
                              void* d_out, int out_size) {
    const float* x    = (const float*)d_in[0];
    const float* acts = (const float*)d_in[1];
    const float* wup  = (const float*)d_in[2];
    const float* v1   = (const float*)d_in[3];
    const float* w2   = (const float*)d_in[4];
    float* out = (float*)d_out;

    void *pxh, *pah, *pwup, *pv1, *pw2;
    cudaGetSymbolAddress(&pxh,  g_xh);
    cudaGetSymbolAddress(&pah,  g_ah);
    cudaGetSymbolAddress(&pwup, g_wup);
    cudaGetSymbolAddress(&pv1,  g_v1);
    cudaGetSymbolAddress(&pw2,  g_w2);

    cudaFuncSetAttribute(k_gemm12, cudaFuncAttributeMaxDynamicSharedMemorySize, SMEM12);
    cudaFuncSetAttribute(k_gemm3,  cudaFuncAttributeMaxDynamicSharedMemorySize, SMEM3);

    const int thr = 256, blk = 1184;
    k_cvt<<<blk, thr>>>(x,    (__half*)pxh,  kTok * kH / 4);
    k_cvt<<<blk, thr>>>(acts, (__half*)pah,  kTok * kDL / 4);
    k_cvt<<<blk, thr>>>(wup,  (__half*)pwup, kE * kF * kDL / 4);
    k_cvt<<<blk, thr>>>(v1,   (__half*)pv1,  kE * kF * kH / 4);
    k_cvt<<<blk, thr>>>(w2,   (__half*)pw2,  kE * kF * kH / 4);

    dim3 g12(kF / BN, kTPE / BM, kE);   // 16 x 8 x 8 = 1024 CTAs
    k_gemm12<<<g12, THREADS, SMEM12>>>();

    dim3 g3(kH / BN, kTPE / BM, kE);    // 4 x 8 x 8 = 256 CTAs
    k_gemm3<<<g3, THREADS, SMEM3>>>(out);
}